// round 15
// baseline (speedup 1.0000x reference)
#include <cuda_runtime.h>
#include <cuda_bf16.h>
#include <cuda_fp16.h>

#define Bsz 64
#define Lsz 500
#define Dsz 300
#define Fsz 100
#define IDs 32
#define BL  (Bsz*Lsz)   // 32000
#define KP  320         // padded K (and padded N) for the doc GEMM
#define NK  20          // KP / 16 k-iterations
#define KA  112         // padded F for the attention GEMM (7 x 16)
#define STG_G 9216u     // gemm smem stage: A 128x48B + B 64x48B
#define VSTG 15360u     // att V-chunk stage: 64 rows x 240B

// ---------------- scratch (static device globals; no allocation) ----------------
__device__ __align__(16) __half g_A[2][BL*KP];    // gathered emb, fp16, ungated
__device__ __align__(16) __half g_W[2][KP*KP];    // doc-conv weights fp16, [n][k]
__device__ float g_dots[2][BL*3];
__device__ __align__(16) __half g_C[2][BL*300];   // GEMM out, fp16 packed
__device__ __align__(16) __half g_utf[2][BL*KA];  // conv feature fp16 (att + head)
__device__ float g_nrm[2][BL];
__device__ float g_att[2][BL];

__device__ __forceinline__ float warpSum(float v) {
#pragma unroll
    for (int o = 16; o; o >>= 1) v += __shfl_down_sync(0xffffffffu, v, o);
    return v;
}

__device__ __forceinline__ void ldsm4(unsigned& r0, unsigned& r1,
                                      unsigned& r2, unsigned& r3, unsigned addr) {
    asm volatile("ldmatrix.sync.aligned.m8n8.x4.shared.b16 {%0,%1,%2,%3}, [%4];"
                 : "=r"(r0), "=r"(r1), "=r"(r2), "=r"(r3) : "r"(addr));
}

__device__ __forceinline__ void mma_fp16(float* c, const unsigned* a, const unsigned* b) {
    asm volatile(
        "mma.sync.aligned.m16n8k16.row.col.f32.f16.f16.f32 "
        "{%0,%1,%2,%3}, {%4,%5,%6,%7}, {%8,%9}, {%0,%1,%2,%3};\n"
        : "+f"(c[0]), "+f"(c[1]), "+f"(c[2]), "+f"(c[3])
        : "r"(a[0]), "r"(a[1]), "r"(a[2]), "r"(a[3]), "r"(b[0]), "r"(b[1]));
}

__device__ __forceinline__ void cp16(unsigned sdst, const void* gsrc) {
    asm volatile("cp.async.cg.shared.global [%0], [%1], 16;" :: "r"(sdst), "l"(gsrc));
}
__device__ __forceinline__ void cp16z(unsigned sdst, const void* gsrc, bool v) {
    int sz = v ? 16 : 0;
    asm volatile("cp.async.cg.shared.global [%0], [%1], 16, %2;" :: "r"(sdst), "l"(gsrc), "r"(sz));
}
__device__ __forceinline__ void cp_commit() { asm volatile("cp.async.commit_group;"); }
template <int N>
__device__ __forceinline__ void cp_wait() { asm volatile("cp.async.wait_group %0;" :: "n"(N)); }

__device__ __forceinline__ unsigned s2u(const void* p) {
    unsigned a;
    asm("{ .reg .u64 t; cvta.to.shared.u64 t, %1; cvt.u32.u64 %0, t; }" : "=r"(a) : "l"(p));
    return a;
}

__device__ __forceinline__ unsigned packh(float a, float b) {
    __half ha = __float2half(a), hb = __float2half(b);
    return (unsigned)__half_as_ushort(ha) | ((unsigned)__half_as_ushort(hb) << 16);
}

// ---------------- K0: repack doc-conv weights fp16 -> [n][k] padded ----------------
__global__ void k_prep(const float* __restrict__ uw, const float* __restrict__ iw) {
    int idx = blockIdx.x * 256 + threadIdx.x;
    if (idx >= 2 * KP * KP) return;
    int side = idx / (KP * KP);
    int r = idx - side * KP * KP;
    int n = r / KP, k = r % KP;
    float x = 0.f;
    if (n < 300 && k < 300) {
        int f = n % Fsz, ks = n / Fsz;
        const float* w = side ? iw : uw;
        x = w[(f * 3 + ks) * Dsz + k];
    }
    g_W[side][n * KP + k] = __float2half(x);
}

// ---------------- K1: gather, warp-per-row (no smem, no barriers) ----------------
__global__ __launch_bounds__(256) void k_gather(
        const int* __restrict__ udoc, const int* __restrict__ idoc,
        const float* __restrict__ uemb, const float* __restrict__ iemb,
        const float* __restrict__ wc) {
    const int side = blockIdx.y;
    const int warp = threadIdx.x >> 5, lane = threadIdx.x & 31;
    const int bl = blockIdx.x * 8 + warp;
    const int* doc = side ? idoc : udoc;
    const float* emb = side ? iemb : uemb;
    const int row = doc[bl];
    const float* e = emb + (size_t)row * Dsz;
    unsigned* ad = reinterpret_cast<unsigned*>(&g_A[side][(size_t)bl * KP]);
    float p0 = 0.f, p1 = 0.f, p2 = 0.f;
#pragma unroll
    for (int k = 0; k < 5; k++) {
        const int idx = lane + 32 * k;   // float2 index, 0..159
        const int d = 2 * idx;
        float x0 = 0.f, x1 = 0.f;
        if (d < 300) {
            float2 v = *reinterpret_cast<const float2*>(&e[d]);
            x0 = v.x; x1 = v.y;
            p0 += x0 * wc[d]       + x1 * wc[d + 1];
            p1 += x0 * wc[300 + d] + x1 * wc[301 + d];
            p2 += x0 * wc[600 + d] + x1 * wc[601 + d];
        }
        ad[idx] = packh(x0, x1);
    }
    p0 = warpSum(p0); p1 = warpSum(p1); p2 = warpSum(p2);
    if (lane == 0) {
        g_dots[side][bl * 3 + 0] = p0;
        g_dots[side][bl * 3 + 1] = p1;
        g_dots[side][bl * 3 + 2] = p2;
    }
}

// ---------------- K3: fp16 single-pass mma GEMM, fp16 packed C output ----------------
__global__ __launch_bounds__(256, 3) void k_gemm_fp16() {
    const int side = blockIdx.z;
    unsigned* __restrict__ Cm = reinterpret_cast<unsigned*>(g_C[side]);

    extern __shared__ __align__(16) unsigned char smbuf[];   // 4 x 9216

    const int tid = threadIdx.x;
    const int lane = tid & 31, wid = tid >> 5;
    const int wm = wid >> 1, wn = wid & 1;
    const int n0 = blockIdx.x * 64;
    const int m0 = blockIdx.y * 128;

    const unsigned smem0 = s2u(&smbuf[0]);

    const int arow = tid >> 1, ahalf = tid & 1;
    const char* gA = (const char*)&g_A[side][((size_t)(m0 + arow)) * KP + ahalf * 8];
    const unsigned sA = smem0 + arow * 48 + ahalf * 16;
    const int brow = tid >> 1;
    const char* gB = (const char*)&g_W[side][((size_t)(n0 + (brow & 63))) * KP + ahalf * 8];
    const unsigned sB = smem0 + 6144u + (brow & 63) * 48 + ahalf * 16;
    const bool hasB = tid < 128;

    float acc[2][4][4];
#pragma unroll
    for (int i = 0; i < 2; i++)
#pragma unroll
        for (int j = 0; j < 4; j++)
#pragma unroll
            for (int q = 0; q < 4; q++) acc[i][j][q] = 0.f;

#pragma unroll
    for (int s = 0; s < 3; s++) {
        cp16(sA + s * STG_G, gA + s * 32);
        if (hasB) cp16(sB + s * STG_G, gB + s * 32);
        cp_commit();
    }

    const int l4 = lane & 7, g4 = lane >> 3;
    unsigned aoff[2];
#pragma unroll
    for (int mt = 0; mt < 2; mt++) {
        int rowm = wm * 32 + mt * 16 + (g4 & 1) * 8 + l4;
        aoff[mt] = smem0 + rowm * 48 + (g4 >> 1) * 16;
    }
    unsigned boff[2];
#pragma unroll
    for (int ntp = 0; ntp < 2; ntp++) {
        int rown = wn * 32 + ntp * 16 + (g4 >> 1) * 8 + l4;
        boff[ntp] = smem0 + 6144u + rown * 48 + (g4 & 1) * 16;
    }

    for (int it = 0; it < NK; it++) {
        const unsigned sbase = (unsigned)(it & 3) * STG_G;
        if (it < NK - 3) cp_wait<2>(); else cp_wait<0>();
        __syncthreads();

        if (it + 3 < NK) {
            const unsigned nb = (unsigned)((it + 3) & 3) * STG_G;
            cp16(sA + nb, gA + (it + 3) * 32);
            if (hasB) cp16(sB + nb, gB + (it + 3) * 32);
            cp_commit();
        }

        unsigned a[2][4], b[2][4];
#pragma unroll
        for (int mt = 0; mt < 2; mt++)
            ldsm4(a[mt][0], a[mt][1], a[mt][2], a[mt][3], aoff[mt] + sbase);
#pragma unroll
        for (int ntp = 0; ntp < 2; ntp++)
            ldsm4(b[ntp][0], b[ntp][1], b[ntp][2], b[ntp][3], boff[ntp] + sbase);
#pragma unroll
        for (int mt = 0; mt < 2; mt++)
#pragma unroll
            for (int nt = 0; nt < 4; nt++)
                mma_fp16(acc[mt][nt], a[mt], &b[nt >> 1][(nt & 1) * 2]);
    }

#pragma unroll
    for (int mt = 0; mt < 2; mt++) {
        int r = m0 + wm * 32 + mt * 16 + (lane >> 2);
#pragma unroll
        for (int nt = 0; nt < 4; nt++) {
            int c = n0 + wn * 32 + nt * 8 + 2 * (lane & 3);   // always even
            if (c < 300) {
                Cm[((size_t)r * 300 + c) >> 1]       = packh(acc[mt][nt][0], acc[mt][nt][1]);
                Cm[((size_t)(r + 8) * 300 + c) >> 1] = packh(acc[mt][nt][2], acc[mt][nt][3]);
            }
        }
    }
}

// ---------------- K4: combine (gate inline) -> utf fp16, norms, zero att --------------
__global__ __launch_bounds__(256) void k_comb(const float* __restrict__ udb,
                                              const float* __restrict__ idb,
                                              const float* __restrict__ wcb) {
    const int side = blockIdx.z;
    const int b = blockIdx.y;
    const int lbase = blockIdx.x * 32;
    const float* bias = side ? idb : udb;
    const __half2* C2 = reinterpret_cast<const __half2*>(g_C[side]) + (size_t)b * Lsz * 150;
    const float* dots = g_dots[side] + (size_t)b * Lsz * 3;
    __half* utf = g_utf[side] + (size_t)b * Lsz * KA;

    __shared__ float sgv[34];
    const float wb = wcb[0];
    if (threadIdx.x < 34) {
        int l = lbase - 1 + threadIdx.x;
        float gv = 0.f;
        if (l >= 0 && l < Lsz) {
            float g = dots[l * 3 + 1] + wb;
            if (l >= 1)        g += dots[(l - 1) * 3 + 0];
            if (l <= Lsz - 2)  g += dots[(l + 1) * 3 + 2];
            gv = 1.f / (1.f + __expf(-g));
        }
        sgv[threadIdx.x] = gv;
    }
    __syncthreads();

    const int warp = threadIdx.x >> 5, lane = threadIdx.x & 31;
#pragma unroll
    for (int po = 0; po < 4; po++) {
        const int lo = po * 8 + warp;
        const int l = lbase + lo;
        if (l >= Lsz) break;
        const float gm = sgv[lo];
        const float gc = sgv[lo + 1];
        const float gp = sgv[lo + 2];
        unsigned* urow = reinterpret_cast<unsigned*>(utf + (size_t)l * KA);
        float nr = 0.f;
#pragma unroll
        for (int half = 0; half < 2; half++) {
            const int f0 = half * 64 + 2 * lane;   // even
            float v0 = 0.f, v1 = 0.f;
            if (f0 < Fsz) {
                float2 vc = __half22float2(C2[(size_t)l * 150 + (100 + f0) / 2]);
                v0 = bias[f0] + gc * vc.x;
                v1 = bias[f0 + 1] + gc * vc.y;
                if (l >= 1) {
                    float2 vm = __half22float2(C2[(size_t)(l - 1) * 150 + f0 / 2]);
                    v0 += gm * vm.x; v1 += gm * vm.y;
                }
                if (l < Lsz - 1) {
                    float2 vp = __half22float2(C2[(size_t)(l + 1) * 150 + (200 + f0) / 2]);
                    v0 += gp * vp.x; v1 += gp * vp.y;
                }
            }
            __half h0 = __float2half(v0);
            __half h1 = __float2half(v1);
            if (f0 < KA)
                urow[half * 32 + lane] =
                    (unsigned)__half_as_ushort(h0) | ((unsigned)__half_as_ushort(h1) << 16);
            float g0 = __half2float(h0), g1 = __half2float(h1);
            nr += g0 * g0 + g1 * g1;
        }
        nr = warpSum(nr);
        if (lane == 0) {
            g_nrm[side][b * Lsz + l] = nr;
            g_att[side][b * Lsz + l] = 0.f;
        }
    }
}

// ---------------- K5: l-strip attention: U staged once, V streamed (3-buf) ----------
// grid (8 l-strips, 1, B), 256 threads. smem: U @0 (15360B), V bufs @15360+15360*buf.
// Side-0 row sums complete per block -> plain store; side-1 col sums via atomics.
__global__ __launch_bounds__(256) void k_att_strip() {
    extern __shared__ __align__(16) unsigned char sm[];
    __shared__ float rsum[64], csum[64];
    const int b = blockIdx.z;
    const int l0 = blockIdx.x * 64;
    const int tid = threadIdx.x;
    const int lane = tid & 31, wid = tid >> 5;
    const int wm2 = wid >> 2, wn2 = wid & 3;
    const unsigned sbase = s2u(&sm[0]);

    if (tid < 64) { rsum[tid] = 0.f; csum[tid] = 0.f; }

    // stage U strip (group with V chunk 0)
    for (int i = tid; i < 896; i += 256) {
        int r = i / 14, c = i - r * 14;
        int row = l0 + r;
        bool valid = row < Lsz;
        const __half* src = g_utf[0] + ((size_t)(b * Lsz + (valid ? row : 0))) * KA + c * 8;
        cp16z(sbase + r * 240 + c * 16, src, valid);
    }
    // V chunk loader
    auto loadV = [&](int mc, int buf) {
        const unsigned vb = sbase + VSTG * (unsigned)(1 + buf);
        for (int i = tid; i < 896; i += 256) {
            int r = i / 14, c = i - r * 14;
            int row = mc * 64 + r;
            bool valid = row < Lsz;
            const __half* src = g_utf[1] + ((size_t)(b * Lsz + (valid ? row : 0))) * KA + c * 8;
            cp16z(vb + r * 240 + c * 16, src, valid);
        }
    };
    loadV(0, 0);
    cp_commit();          // group: U + V0
    loadV(1, 1);
    cp_commit();          // group: V1

    // fragment offsets
    const int l4 = lane & 7, g4 = lane >> 3;
    unsigned aoff[2];
#pragma unroll
    for (int mt = 0; mt < 2; mt++) {
        int rowm = wm2 * 32 + mt * 16 + (g4 & 1) * 8 + l4;
        int koff = (g4 >> 1) * 8;
        aoff[mt] = sbase + (rowm * 120 + koff) * 2;
    }
    unsigned boff_rel;
    {
        int rown = wn2 * 16 + (g4 >> 1) * 8 + l4;
        int koff = (g4 & 1) * 8;
        boff_rel = (unsigned)(rown * 120 + koff) * 2;
    }

    // norms for this l-strip (constant across chunks)
    float nu[2][2];
#pragma unroll
    for (int mt = 0; mt < 2; mt++)
#pragma unroll
        for (int h = 0; h < 2; h++) {
            int l = l0 + wm2 * 32 + mt * 16 + h * 8 + (lane >> 2);
            nu[mt][h] = (l < Lsz) ? g_nrm[0][b * Lsz + l] : 0.f;
        }

    float rsv[4] = {0.f, 0.f, 0.f, 0.f};

    for (int j = 0; j < 8; j++) {
        if (j < 7) cp_wait<1>(); else cp_wait<0>();
        __syncthreads();                       // chunk j visible; prev compute done
        if (j + 2 < 8) { loadV(j + 2, (j + 2) % 3); cp_commit(); }

        const unsigned vb = sbase + VSTG * (unsigned)(1 + j % 3);
        const int m0 = j * 64;

        float acc[2][2][4];
#pragma unroll
        for (int i = 0; i < 2; i++)
#pragma unroll
            for (int jj = 0; jj < 2; jj++)
#pragma unroll
                for (int q = 0; q < 4; q++) acc[i][jj][q] = 0.f;

#pragma unroll
        for (int ck = 0; ck < 7; ck++) {
            const unsigned kb = ck * 32;
            unsigned a[2][4], bfr[4];
#pragma unroll
            for (int mt = 0; mt < 2; mt++)
                ldsm4(a[mt][0], a[mt][1], a[mt][2], a[mt][3], aoff[mt] + kb);
            ldsm4(bfr[0], bfr[1], bfr[2], bfr[3], vb + boff_rel + kb);
#pragma unroll
            for (int mt = 0; mt < 2; mt++)
#pragma unroll
                for (int nt = 0; nt < 2; nt++)
                    mma_fp16(acc[mt][nt], a[mt], &bfr[nt * 2]);
        }

        float nv[2][2];
#pragma unroll
        for (int nt = 0; nt < 2; nt++)
#pragma unroll
            for (int cc = 0; cc < 2; cc++) {
                int m = m0 + wn2 * 16 + nt * 8 + 2 * (lane & 3) + cc;
                nv[nt][cc] = (m < Lsz) ? g_nrm[1][b * Lsz + m] : 0.f;
            }

        float csv[4] = {0.f, 0.f, 0.f, 0.f};
#pragma unroll
        for (int mt = 0; mt < 2; mt++)
#pragma unroll
            for (int nt = 0; nt < 2; nt++)
#pragma unroll
                for (int q = 0; q < 4; q++) {
                    int h = q >> 1, cc = q & 1;
                    int l = l0 + wm2 * 32 + mt * 16 + h * 8 + (lane >> 2);
                    int m = m0 + wn2 * 16 + nt * 8 + 2 * (lane & 3) + cc;
                    if (l < Lsz && m < Lsz) {
                        float sq = nu[mt][h] + nv[nt][cc] - 2.f * acc[mt][nt][q];
                        float a = 1.f / (1.f + sqrtf(fmaxf(sq, 1e-12f)));
                        rsv[mt * 2 + h] += a;
                        csv[nt * 2 + cc] += a;
                    }
                }
#pragma unroll
        for (int q = 0; q < 4; q++)
            atomicAdd(&csum[wn2 * 16 + (q >> 1) * 8 + 2 * (lane & 3) + (q & 1)], csv[q]);
        __syncthreads();
        if (tid < 64) {
            int m = m0 + tid;
            if (m < Lsz && csum[tid] != 0.f) atomicAdd(&g_att[1][b * Lsz + m], csum[tid]);
            csum[tid] = 0.f;
        }
        // re-zero separated from next chunk's atomics by next iteration's __syncthreads
    }

    // flush complete row sums (plain store)
#pragma unroll
    for (int q = 0; q < 4; q++)
        atomicAdd(&rsum[wm2 * 32 + (q >> 1) * 16 + (q & 1) * 8 + (lane >> 2)], rsv[q]);
    __syncthreads();
    if (tid < 64 && l0 + tid < Lsz) g_att[0][b * Lsz + l0 + tid] = rsum[tid];
}

// ---------------- K6: head via closed-form pooling (4-way l-split) -------------------
__global__ __launch_bounds__(512) void k_head(
                       const float* __restrict__ uacw, const float* __restrict__ uacb,
                       const float* __restrict__ iacw, const float* __restrict__ iacb,
                       const float* __restrict__ ufw,  const float* __restrict__ ufb,
                       const float* __restrict__ ifw,  const float* __restrict__ ifb,
                       const int* __restrict__ uids,   const int* __restrict__ iids,
                       const float* __restrict__ uide, const float* __restrict__ iide,
                       float* __restrict__ out) {
    int b = blockIdx.x;
    int side = blockIdx.y;
    const __half* ut = g_utf[side] + (size_t)b * Lsz * KA;
    const float* att = g_att[side] + b * Lsz;
    const float* acw = side ? iacw : uacw;
    const float* acb = side ? iacb : uacb;
    const float* fw  = side ? ifw : ufw;
    const float* fb  = side ? ifb : ufb;
    __shared__ float satt[Lsz];
    __shared__ float sp[4][KA];
    __shared__ float sedge[6][KA];
    __shared__ float S[3][Fsz];
    __shared__ float am[Fsz];
    const int tid = threadIdx.x;

    for (int i = tid; i < Lsz; i += 512) satt[i] = att[i];
    __syncthreads();

    const int g = tid >> 7, tg = tid & 127;
    if (tg < KA) {
        float acc = 0.f;
        const int la = g * 125, lb2 = la + 125;
        for (int l = la; l < lb2; l++) {
            float p = __half2float(ut[(size_t)l * KA + tg]) * satt[l];
            acc += p;
            if (l < 3) sedge[l][tg] = p;
            else if (l >= 497) sedge[l - 494][tg] = p;
        }
        sp[g][tg] = acc;
    }
    __syncthreads();
    if (tid < Fsz) {
        float P3 = 3.f * (sp[0][tid] + sp[1][tid] + sp[2][tid] + sp[3][tid]);
        float p0 = sedge[0][tid], p1 = sedge[1][tid], p2 = sedge[2][tid];
        float q2 = sedge[3][tid], q1 = sedge[4][tid], q0 = sedge[5][tid];
        S[0][tid] = P3 -       p0              -       q2 - 2.f * q1 - 3.f * q0;
        S[1][tid] = P3 - 2.f * p0 -       p1              -       q1 - 2.f * q0;
        S[2][tid] = P3 - 3.f * p0 - 2.f * p1 - p2                    -       q0;
    }
    __syncthreads();
    if (tid < Fsz) {
        float a = 0.f;
#pragma unroll
        for (int k = 0; k < 3; k++)
            for (int gg = 0; gg < Fsz; gg++)
                a += S[k][gg] * acw[(tid * 3 + k) * Fsz + gg];
        am[tid] = acb[tid] + a * (1.f / (float)(Lsz - 2));
    }
    __syncthreads();
    if (tid < IDs) {
        float o = fb[tid];
        for (int f = 0; f < Fsz; f++) o += am[f] * fw[tid * Fsz + f];
        o = fmaxf(o, 0.f);
        int base = side ? (Bsz * 2 * IDs) : 0;
        out[base + (b * 2 + 0) * IDs + tid] = o;
    }
    if (tid >= 64 && tid < 64 + IDs) {
        int i = tid - 64;
        if (side == 0) {
            out[(b * 2 + 1) * IDs + i] = iide[(size_t)iids[b] * IDs + i];
        } else {
            out[Bsz * 2 * IDs + (b * 2 + 1) * IDs + i] = uide[(size_t)uids[b] * IDs + i];
        }
    }
}

// ---------------- launch ----------------
extern "C" void kernel_launch(void* const* d_in, const int* in_sizes, int n_in,
                              void* d_out, int out_size) {
    const int*   uids = (const int*)d_in[0];
    const int*   iids = (const int*)d_in[1];
    const int*   udoc = (const int*)d_in[2];
    const int*   idoc = (const int*)d_in[3];
    const float* uemb = (const float*)d_in[4];
    const float* iemb = (const float*)d_in[5];
    const float* wcw  = (const float*)d_in[6];
    const float* wcb  = (const float*)d_in[7];
    const float* udcw = (const float*)d_in[8];
    const float* udcb = (const float*)d_in[9];
    const float* idcw = (const float*)d_in[10];
    const float* idcb = (const float*)d_in[11];
    const float* uacw = (const float*)d_in[12];
    const float* uacb = (const float*)d_in[13];
    const float* iacw = (const float*)d_in[14];
    const float* iacb = (const float*)d_in[15];
    const float* ufw  = (const float*)d_in[16];
    const float* ufb  = (const float*)d_in[17];
    const float* ifw  = (const float*)d_in[18];
    const float* ifb  = (const float*)d_in[19];
    const float* uide = (const float*)d_in[20];
    const float* iide = (const float*)d_in[21];
    float* out = (float*)d_out;

    cudaFuncSetAttribute(k_gemm_fp16,  cudaFuncAttributeMaxDynamicSharedMemorySize, 4 * (int)STG_G);
    cudaFuncSetAttribute(k_att_strip,  cudaFuncAttributeMaxDynamicSharedMemorySize, 4 * (int)VSTG);

    k_prep<<<(2 * KP * KP + 255) / 256, 256>>>(udcw, idcw);
    k_gather<<<dim3(BL / 8, 2), 256>>>(udoc, idoc, uemb, iemb, wcw);
    k_gemm_fp16<<<dim3(5, 250, 2), 256, 4 * STG_G>>>();
    k_comb<<<dim3(16, Bsz, 2), 256>>>(udcb, idcb, wcb);
    k_att_strip<<<dim3(8, 1, Bsz), 256, 4 * VSTG>>>();
    k_head<<<dim3(Bsz, 2), 512>>>(uacw, uacb, iacw, iacb, ufw, ufb, ifw, ifb,
                                  uids, iids, uide, iide, out);
}

// round 16
// speedup vs baseline: 1.1486x; 1.1486x over previous
#include <cuda_runtime.h>
#include <cuda_bf16.h>
#include <cuda_fp16.h>

#define Bsz 64
#define Lsz 500
#define Dsz 300
#define Fsz 100
#define IDs 32
#define BL  (Bsz*Lsz)   // 32000
#define KP  320         // padded K (and padded N) for the doc GEMM
#define NK  20          // KP / 16 k-iterations
#define KA  112         // padded F for the attention GEMM (7 x 16)
#define STG_G 9216u     // gemm smem stage: A 128x48B + B 64x48B

// ---------------- scratch (static device globals; no allocation) ----------------
__device__ __align__(16) __half g_A[2][BL*KP];    // gathered emb, fp16, ungated
__device__ __align__(16) __half g_W[2][KP*KP];    // doc-conv weights fp16, [n][k]
__device__ float g_dots[2][BL*3];
__device__ __align__(16) __half g_C[2][BL*300];   // GEMM out, fp16 packed
__device__ __align__(16) __half g_utf[2][BL*KA];  // conv feature fp16 (att + head)
__device__ float g_nrm[2][BL];
__device__ float g_att[2][BL];

__device__ __forceinline__ float warpSum(float v) {
#pragma unroll
    for (int o = 16; o; o >>= 1) v += __shfl_down_sync(0xffffffffu, v, o);
    return v;
}

__device__ __forceinline__ void ldsm4(unsigned& r0, unsigned& r1,
                                      unsigned& r2, unsigned& r3, unsigned addr) {
    asm volatile("ldmatrix.sync.aligned.m8n8.x4.shared.b16 {%0,%1,%2,%3}, [%4];"
                 : "=r"(r0), "=r"(r1), "=r"(r2), "=r"(r3) : "r"(addr));
}

__device__ __forceinline__ void mma_fp16(float* c, const unsigned* a, const unsigned* b) {
    asm volatile(
        "mma.sync.aligned.m16n8k16.row.col.f32.f16.f16.f32 "
        "{%0,%1,%2,%3}, {%4,%5,%6,%7}, {%8,%9}, {%0,%1,%2,%3};\n"
        : "+f"(c[0]), "+f"(c[1]), "+f"(c[2]), "+f"(c[3])
        : "r"(a[0]), "r"(a[1]), "r"(a[2]), "r"(a[3]), "r"(b[0]), "r"(b[1]));
}

__device__ __forceinline__ void cp16(unsigned sdst, const void* gsrc) {
    asm volatile("cp.async.cg.shared.global [%0], [%1], 16;" :: "r"(sdst), "l"(gsrc));
}
__device__ __forceinline__ void cp16z(unsigned sdst, const void* gsrc, bool v) {
    int sz = v ? 16 : 0;
    asm volatile("cp.async.cg.shared.global [%0], [%1], 16, %2;" :: "r"(sdst), "l"(gsrc), "r"(sz));
}
__device__ __forceinline__ void cp_commit() { asm volatile("cp.async.commit_group;"); }
template <int N>
__device__ __forceinline__ void cp_wait() { asm volatile("cp.async.wait_group %0;" :: "n"(N)); }

__device__ __forceinline__ unsigned s2u(const void* p) {
    unsigned a;
    asm("{ .reg .u64 t; cvta.to.shared.u64 t, %1; cvt.u32.u64 %0, t; }" : "=r"(a) : "l"(p));
    return a;
}

__device__ __forceinline__ unsigned packh(float a, float b) {
    __half ha = __float2half(a), hb = __float2half(b);
    return (unsigned)__half_as_ushort(ha) | ((unsigned)__half_as_ushort(hb) << 16);
}

// ---------------- K0: repack doc-conv weights fp16 -> [n][k] padded ----------------
__global__ void k_prep(const float* __restrict__ uw, const float* __restrict__ iw) {
    int idx = blockIdx.x * 256 + threadIdx.x;
    if (idx >= 2 * KP * KP) return;
    int side = idx / (KP * KP);
    int r = idx - side * KP * KP;
    int n = r / KP, k = r % KP;
    float x = 0.f;
    if (n < 300 && k < 300) {
        int f = n % Fsz, ks = n / Fsz;
        const float* w = side ? iw : uw;
        x = w[(f * 3 + ks) * Dsz + k];
    }
    g_W[side][n * KP + k] = __float2half(x);
}

// ---------------- K1: gather, warp-per-row (no smem, no barriers) ----------------
__global__ __launch_bounds__(256) void k_gather(
        const int* __restrict__ udoc, const int* __restrict__ idoc,
        const float* __restrict__ uemb, const float* __restrict__ iemb,
        const float* __restrict__ wc) {
    const int side = blockIdx.y;
    const int warp = threadIdx.x >> 5, lane = threadIdx.x & 31;
    const int bl = blockIdx.x * 8 + warp;
    const int* doc = side ? idoc : udoc;
    const float* emb = side ? iemb : uemb;
    const int row = doc[bl];
    const float* e = emb + (size_t)row * Dsz;
    unsigned* ad = reinterpret_cast<unsigned*>(&g_A[side][(size_t)bl * KP]);
    float p0 = 0.f, p1 = 0.f, p2 = 0.f;
#pragma unroll
    for (int k = 0; k < 5; k++) {
        const int idx = lane + 32 * k;   // float2 index, 0..159
        const int d = 2 * idx;
        float x0 = 0.f, x1 = 0.f;
        if (d < 300) {
            float2 v = *reinterpret_cast<const float2*>(&e[d]);
            x0 = v.x; x1 = v.y;
            p0 += x0 * wc[d]       + x1 * wc[d + 1];
            p1 += x0 * wc[300 + d] + x1 * wc[301 + d];
            p2 += x0 * wc[600 + d] + x1 * wc[601 + d];
        }
        ad[idx] = packh(x0, x1);
    }
    p0 = warpSum(p0); p1 = warpSum(p1); p2 = warpSum(p2);
    if (lane == 0) {
        g_dots[side][bl * 3 + 0] = p0;
        g_dots[side][bl * 3 + 1] = p1;
        g_dots[side][bl * 3 + 2] = p2;
    }
}

// ---------------- K3: fp16 single-pass mma GEMM, fp16 packed C output ----------------
__global__ __launch_bounds__(256, 3) void k_gemm_fp16() {
    const int side = blockIdx.z;
    unsigned* __restrict__ Cm = reinterpret_cast<unsigned*>(g_C[side]);

    extern __shared__ __align__(16) unsigned char smbuf[];   // 4 x 9216

    const int tid = threadIdx.x;
    const int lane = tid & 31, wid = tid >> 5;
    const int wm = wid >> 1, wn = wid & 1;
    const int n0 = blockIdx.x * 64;
    const int m0 = blockIdx.y * 128;

    const unsigned smem0 = s2u(&smbuf[0]);

    const int arow = tid >> 1, ahalf = tid & 1;
    const char* gA = (const char*)&g_A[side][((size_t)(m0 + arow)) * KP + ahalf * 8];
    const unsigned sA = smem0 + arow * 48 + ahalf * 16;
    const int brow = tid >> 1;
    const char* gB = (const char*)&g_W[side][((size_t)(n0 + (brow & 63))) * KP + ahalf * 8];
    const unsigned sB = smem0 + 6144u + (brow & 63) * 48 + ahalf * 16;
    const bool hasB = tid < 128;

    float acc[2][4][4];
#pragma unroll
    for (int i = 0; i < 2; i++)
#pragma unroll
        for (int j = 0; j < 4; j++)
#pragma unroll
            for (int q = 0; q < 4; q++) acc[i][j][q] = 0.f;

#pragma unroll
    for (int s = 0; s < 3; s++) {
        cp16(sA + s * STG_G, gA + s * 32);
        if (hasB) cp16(sB + s * STG_G, gB + s * 32);
        cp_commit();
    }

    const int l4 = lane & 7, g4 = lane >> 3;
    unsigned aoff[2];
#pragma unroll
    for (int mt = 0; mt < 2; mt++) {
        int rowm = wm * 32 + mt * 16 + (g4 & 1) * 8 + l4;
        aoff[mt] = smem0 + rowm * 48 + (g4 >> 1) * 16;
    }
    unsigned boff[2];
#pragma unroll
    for (int ntp = 0; ntp < 2; ntp++) {
        int rown = wn * 32 + ntp * 16 + (g4 >> 1) * 8 + l4;
        boff[ntp] = smem0 + 6144u + rown * 48 + (g4 & 1) * 16;
    }

    for (int it = 0; it < NK; it++) {
        const unsigned sbase = (unsigned)(it & 3) * STG_G;
        if (it < NK - 3) cp_wait<2>(); else cp_wait<0>();
        __syncthreads();

        if (it + 3 < NK) {
            const unsigned nb = (unsigned)((it + 3) & 3) * STG_G;
            cp16(sA + nb, gA + (it + 3) * 32);
            if (hasB) cp16(sB + nb, gB + (it + 3) * 32);
            cp_commit();
        }

        unsigned a[2][4], b[2][4];
#pragma unroll
        for (int mt = 0; mt < 2; mt++)
            ldsm4(a[mt][0], a[mt][1], a[mt][2], a[mt][3], aoff[mt] + sbase);
#pragma unroll
        for (int ntp = 0; ntp < 2; ntp++)
            ldsm4(b[ntp][0], b[ntp][1], b[ntp][2], b[ntp][3], boff[ntp] + sbase);
#pragma unroll
        for (int mt = 0; mt < 2; mt++)
#pragma unroll
            for (int nt = 0; nt < 4; nt++)
                mma_fp16(acc[mt][nt], a[mt], &b[nt >> 1][(nt & 1) * 2]);
    }

#pragma unroll
    for (int mt = 0; mt < 2; mt++) {
        int r = m0 + wm * 32 + mt * 16 + (lane >> 2);
#pragma unroll
        for (int nt = 0; nt < 4; nt++) {
            int c = n0 + wn * 32 + nt * 8 + 2 * (lane & 3);   // always even
            if (c < 300) {
                Cm[((size_t)r * 300 + c) >> 1]       = packh(acc[mt][nt][0], acc[mt][nt][1]);
                Cm[((size_t)(r + 8) * 300 + c) >> 1] = packh(acc[mt][nt][2], acc[mt][nt][3]);
            }
        }
    }
}

// ---------------- K4: combine (gate inline) -> utf fp16, norms, zero att --------------
__global__ __launch_bounds__(256) void k_comb(const float* __restrict__ udb,
                                              const float* __restrict__ idb,
                                              const float* __restrict__ wcb) {
    const int side = blockIdx.z;
    const int b = blockIdx.y;
    const int lbase = blockIdx.x * 32;
    const float* bias = side ? idb : udb;
    const __half2* C2 = reinterpret_cast<const __half2*>(g_C[side]) + (size_t)b * Lsz * 150;
    const float* dots = g_dots[side] + (size_t)b * Lsz * 3;
    __half* utf = g_utf[side] + (size_t)b * Lsz * KA;

    __shared__ float sgv[34];
    const float wb = wcb[0];
    if (threadIdx.x < 34) {
        int l = lbase - 1 + threadIdx.x;
        float gv = 0.f;
        if (l >= 0 && l < Lsz) {
            float g = dots[l * 3 + 1] + wb;
            if (l >= 1)        g += dots[(l - 1) * 3 + 0];
            if (l <= Lsz - 2)  g += dots[(l + 1) * 3 + 2];
            gv = 1.f / (1.f + __expf(-g));
        }
        sgv[threadIdx.x] = gv;
    }
    __syncthreads();

    const int warp = threadIdx.x >> 5, lane = threadIdx.x & 31;
#pragma unroll
    for (int po = 0; po < 4; po++) {
        const int lo = po * 8 + warp;
        const int l = lbase + lo;
        if (l >= Lsz) break;
        const float gm = sgv[lo];
        const float gc = sgv[lo + 1];
        const float gp = sgv[lo + 2];
        unsigned* urow = reinterpret_cast<unsigned*>(utf + (size_t)l * KA);
        float nr = 0.f;
#pragma unroll
        for (int half = 0; half < 2; half++) {
            const int f0 = half * 64 + 2 * lane;   // even
            float v0 = 0.f, v1 = 0.f;
            if (f0 < Fsz) {
                float2 vc = __half22float2(C2[(size_t)l * 150 + (100 + f0) / 2]);
                v0 = bias[f0] + gc * vc.x;
                v1 = bias[f0 + 1] + gc * vc.y;
                if (l >= 1) {
                    float2 vm = __half22float2(C2[(size_t)(l - 1) * 150 + f0 / 2]);
                    v0 += gm * vm.x; v1 += gm * vm.y;
                }
                if (l < Lsz - 1) {
                    float2 vp = __half22float2(C2[(size_t)(l + 1) * 150 + (200 + f0) / 2]);
                    v0 += gp * vp.x; v1 += gp * vp.y;
                }
            }
            __half h0 = __float2half(v0);
            __half h1 = __float2half(v1);
            if (f0 < KA)
                urow[half * 32 + lane] =
                    (unsigned)__half_as_ushort(h0) | ((unsigned)__half_as_ushort(h1) << 16);
            float g0 = __half2float(h0), g1 = __half2float(h1);
            nr += g0 * g0 + g1 * g1;
        }
        nr = warpSum(nr);
        if (lane == 0) {
            g_nrm[side][b * Lsz + l] = nr;
            g_att[side][b * Lsz + l] = 0.f;
        }
    }
}

// ---------------- K5: fp16 single-pass tensor-core pairwise attention (R13 version) ----
__global__ __launch_bounds__(256, 4) void k_att_tc() {
    extern __shared__ __align__(16) unsigned char sm[];
    __shared__ float rsum[64], csum[64];
    const int b = blockIdx.z;
    const int l0 = blockIdx.x * 64, m0 = blockIdx.y * 64;
    const int tid = threadIdx.x;
    const int lane = tid & 31, wid = tid >> 5;
    const int wm2 = wid >> 2, wn2 = wid & 3;
    const unsigned sbase = s2u(&sm[0]);

    if (tid < 64) { rsum[tid] = 0.f; csum[tid] = 0.f; }

    for (int i = tid; i < 2 * 64 * 14; i += 256) {
        int arr = i / 896;
        int rem = i - arr * 896;
        int r = rem / 14, c = rem - r * 14;
        int row = (arr ? m0 : l0) + r;
        bool valid = row < Lsz;
        int srow = valid ? row : 0;
        const __half* src = g_utf[arr] + ((size_t)(b * Lsz + srow)) * KA + c * 8;
        cp16z(sbase + arr * 15360 + r * 240 + c * 16, src, valid);
    }
    cp_commit();
    cp_wait<0>();
    __syncthreads();

    const int l4 = lane & 7, g4 = lane >> 3;
    unsigned aoff[2];
#pragma unroll
    for (int mt = 0; mt < 2; mt++) {
        int rowm = wm2 * 32 + mt * 16 + (g4 & 1) * 8 + l4;
        int koff = (g4 >> 1) * 8;
        aoff[mt] = sbase + (rowm * 120 + koff) * 2;
    }
    unsigned boffv;
    {
        int rown = wn2 * 16 + (g4 >> 1) * 8 + l4;
        int koff = (g4 & 1) * 8;
        boffv = sbase + 15360u + (rown * 120 + koff) * 2;
    }

    float acc[2][2][4];
#pragma unroll
    for (int i = 0; i < 2; i++)
#pragma unroll
        for (int j = 0; j < 2; j++)
#pragma unroll
            for (int q = 0; q < 4; q++) acc[i][j][q] = 0.f;

#pragma unroll
    for (int ck = 0; ck < 7; ck++) {
        const unsigned kb = ck * 32;
        unsigned a[2][4], bfr[4];
#pragma unroll
        for (int mt = 0; mt < 2; mt++)
            ldsm4(a[mt][0], a[mt][1], a[mt][2], a[mt][3], aoff[mt] + kb);
        ldsm4(bfr[0], bfr[1], bfr[2], bfr[3], boffv + kb);
#pragma unroll
        for (int mt = 0; mt < 2; mt++)
#pragma unroll
            for (int nt = 0; nt < 2; nt++)
                mma_fp16(acc[mt][nt], a[mt], &bfr[nt * 2]);
    }

    float nu[2][2], nv[2][2];
#pragma unroll
    for (int mt = 0; mt < 2; mt++)
#pragma unroll
        for (int h = 0; h < 2; h++) {
            int l = l0 + wm2 * 32 + mt * 16 + h * 8 + (lane >> 2);
            nu[mt][h] = (l < Lsz) ? g_nrm[0][b * Lsz + l] : 0.f;
        }
#pragma unroll
    for (int nt = 0; nt < 2; nt++)
#pragma unroll
        for (int cc = 0; cc < 2; cc++) {
            int m = m0 + wn2 * 16 + nt * 8 + 2 * (lane & 3) + cc;
            nv[nt][cc] = (m < Lsz) ? g_nrm[1][b * Lsz + m] : 0.f;
        }

    float rsv[4] = {0, 0, 0, 0}, csv[4] = {0, 0, 0, 0};
#pragma unroll
    for (int mt = 0; mt < 2; mt++)
#pragma unroll
        for (int nt = 0; nt < 2; nt++)
#pragma unroll
            for (int q = 0; q < 4; q++) {
                int h = q >> 1, cc = q & 1;
                int l = l0 + wm2 * 32 + mt * 16 + h * 8 + (lane >> 2);
                int m = m0 + wn2 * 16 + nt * 8 + 2 * (lane & 3) + cc;
                if (l < Lsz && m < Lsz) {
                    float sq = nu[mt][h] + nv[nt][cc] - 2.f * acc[mt][nt][q];
                    float a = 1.f / (1.f + sqrtf(fmaxf(sq, 1e-12f)));
                    rsv[mt * 2 + h] += a;
                    csv[nt * 2 + cc] += a;
                }
            }
#pragma unroll
    for (int q = 0; q < 4; q++) {
        atomicAdd(&rsum[wm2 * 32 + (q >> 1) * 16 + (q & 1) * 8 + (lane >> 2)], rsv[q]);
        atomicAdd(&csum[wn2 * 16 + (q >> 1) * 8 + 2 * (lane & 3) + (q & 1)], csv[q]);
    }
    __syncthreads();
    if (tid < 64) {
        if (l0 + tid < Lsz) atomicAdd(&g_att[0][b * Lsz + l0 + tid], rsum[tid]);
        if (m0 + tid < Lsz) atomicAdd(&g_att[1][b * Lsz + m0 + tid], csum[tid]);
    }
}

// ---------------- K6: head via closed-form pooling (4-way l-split) -------------------
__global__ __launch_bounds__(512) void k_head(
                       const float* __restrict__ uacw, const float* __restrict__ uacb,
                       const float* __restrict__ iacw, const float* __restrict__ iacb,
                       const float* __restrict__ ufw,  const float* __restrict__ ufb,
                       const float* __restrict__ ifw,  const float* __restrict__ ifb,
                       const int* __restrict__ uids,   const int* __restrict__ iids,
                       const float* __restrict__ uide, const float* __restrict__ iide,
                       float* __restrict__ out) {
    int b = blockIdx.x;
    int side = blockIdx.y;
    const __half* ut = g_utf[side] + (size_t)b * Lsz * KA;
    const float* att = g_att[side] + b * Lsz;
    const float* acw = side ? iacw : uacw;
    const float* acb = side ? iacb : uacb;
    const float* fw  = side ? ifw : ufw;
    const float* fb  = side ? ifb : ufb;
    __shared__ float satt[Lsz];
    __shared__ float sp[4][KA];
    __shared__ float sedge[6][KA];
    __shared__ float S[3][Fsz];
    __shared__ float am[Fsz];
    const int tid = threadIdx.x;

    for (int i = tid; i < Lsz; i += 512) satt[i] = att[i];
    __syncthreads();

    const int g = tid >> 7, tg = tid & 127;
    if (tg < KA) {
        float acc = 0.f;
        const int la = g * 125, lb2 = la + 125;
        for (int l = la; l < lb2; l++) {
            float p = __half2float(ut[(size_t)l * KA + tg]) * satt[l];
            acc += p;
            if (l < 3) sedge[l][tg] = p;
            else if (l >= 497) sedge[l - 494][tg] = p;
        }
        sp[g][tg] = acc;
    }
    __syncthreads();
    if (tid < Fsz) {
        float P3 = 3.f * (sp[0][tid] + sp[1][tid] + sp[2][tid] + sp[3][tid]);
        float p0 = sedge[0][tid], p1 = sedge[1][tid], p2 = sedge[2][tid];
        float q2 = sedge[3][tid], q1 = sedge[4][tid], q0 = sedge[5][tid];
        S[0][tid] = P3 -       p0              -       q2 - 2.f * q1 - 3.f * q0;
        S[1][tid] = P3 - 2.f * p0 -       p1              -       q1 - 2.f * q0;
        S[2][tid] = P3 - 3.f * p0 - 2.f * p1 - p2                    -       q0;
    }
    __syncthreads();
    if (tid < Fsz) {
        float a = 0.f;
#pragma unroll
        for (int k = 0; k < 3; k++)
            for (int gg = 0; gg < Fsz; gg++)
                a += S[k][gg] * acw[(tid * 3 + k) * Fsz + gg];
        am[tid] = acb[tid] + a * (1.f / (float)(Lsz - 2));
    }
    __syncthreads();
    if (tid < IDs) {
        float o = fb[tid];
        for (int f = 0; f < Fsz; f++) o += am[f] * fw[tid * Fsz + f];
        o = fmaxf(o, 0.f);
        int base = side ? (Bsz * 2 * IDs) : 0;
        out[base + (b * 2 + 0) * IDs + tid] = o;
    }
    if (tid >= 64 && tid < 64 + IDs) {
        int i = tid - 64;
        if (side == 0) {
            out[(b * 2 + 1) * IDs + i] = iide[(size_t)iids[b] * IDs + i];
        } else {
            out[Bsz * 2 * IDs + (b * 2 + 1) * IDs + i] = uide[(size_t)uids[b] * IDs + i];
        }
    }
}

// ---------------- launch ----------------
extern "C" void kernel_launch(void* const* d_in, const int* in_sizes, int n_in,
                              void* d_out, int out_size) {
    const int*   uids = (const int*)d_in[0];
    const int*   iids = (const int*)d_in[1];
    const int*   udoc = (const int*)d_in[2];
    const int*   idoc = (const int*)d_in[3];
    const float* uemb = (const float*)d_in[4];
    const float* iemb = (const float*)d_in[5];
    const float* wcw  = (const float*)d_in[6];
    const float* wcb  = (const float*)d_in[7];
    const float* udcw = (const float*)d_in[8];
    const float* udcb = (const float*)d_in[9];
    const float* idcw = (const float*)d_in[10];
    const float* idcb = (const float*)d_in[11];
    const float* uacw = (const float*)d_in[12];
    const float* uacb = (const float*)d_in[13];
    const float* iacw = (const float*)d_in[14];
    const float* iacb = (const float*)d_in[15];
    const float* ufw  = (const float*)d_in[16];
    const float* ufb  = (const float*)d_in[17];
    const float* ifw  = (const float*)d_in[18];
    const float* ifb  = (const float*)d_in[19];
    const float* uide = (const float*)d_in[20];
    const float* iide = (const float*)d_in[21];
    float* out = (float*)d_out;

    cudaFuncSetAttribute(k_gemm_fp16, cudaFuncAttributeMaxDynamicSharedMemorySize, 4 * (int)STG_G);
    cudaFuncSetAttribute(k_att_tc,    cudaFuncAttributeMaxDynamicSharedMemorySize, 2 * 15360);

    k_prep<<<(2 * KP * KP + 255) / 256, 256>>>(udcw, idcw);
    k_gather<<<dim3(BL / 8, 2), 256>>>(udoc, idoc, uemb, iemb, wcw);
    k_gemm_fp16<<<dim3(5, 250, 2), 256, 4 * STG_G>>>();
    k_comb<<<dim3(16, Bsz, 2), 256>>>(udcb, idcb, wcb);
    k_att_tc<<<dim3(8, 8, Bsz), 256, 2 * 15360>>>();
    k_head<<<dim3(Bsz, 2), 512>>>(uacw, uacb, iacw, iacb, ufw, ufb, ifw, ifb,
                                  uids, iids, uide, iide, out);
}